// round 9
// baseline (speedup 1.0000x reference)
#include <cuda_runtime.h>
#include <cstdint>

#define B_    4
#define H_    8
#define TK_   512
#define NK_   511
#define L_    1023
#define D_    512
#define HD_   64
#define BH_   32
#define ROWS_ 4092          // B_*L_

// Scratch (static __device__ — no allocations allowed)
__device__ float g_q[B_*H_*L_*HD_];
__device__ float g_k[B_*H_*L_*HD_];
__device__ float g_v[B_*H_*L_*HD_];
__device__ float g_ao[B_*L_*D_];            // attention output, (B,L, H*HD)

// ---------------------------------------------------------------------------
// tf32 helpers
// ---------------------------------------------------------------------------
__device__ __forceinline__ void split_tf32(float x, uint32_t& hi, uint32_t& lo)
{
    float h, l2;
    asm("cvt.rna.tf32.f32 %0, %1;" : "=f"(h) : "f"(x));
    float l = x - h;
    asm("cvt.rna.tf32.f32 %0, %1;" : "=f"(l2) : "f"(l));
    hi = __float_as_uint(h);
    lo = __float_as_uint(l2);
}

#define MMA_TF32(d, a, b)                                                     \
    asm volatile(                                                             \
        "mma.sync.aligned.m16n8k8.row.col.f32.tf32.tf32.f32 "                 \
        "{%0,%1,%2,%3}, {%4,%5,%6,%7}, {%8,%9}, {%0,%1,%2,%3};"               \
        : "+f"((d)[0]), "+f"((d)[1]), "+f"((d)[2]), "+f"((d)[3])              \
        : "r"((a)[0]), "r"((a)[1]), "r"((a)[2]), "r"((a)[3]),                 \
          "r"((b)[0]), "r"((b)[1]))

// GEMM kernels: k-chunk = 32 -> stride 36
#define AST_ 36
#define GEMM_SMEM_BYTES ((2*128*AST_ + 2*64*AST_) * 4)   // 55296
// Flash tiles hold full k=64 -> stride 68 (proven in round 7)
#define FST_ 68
#define FLASH_SMEM (6*64*FST_*4 + 2*64*4)                // 104960

// ---------------------------------------------------------------------------
// Kernel 1: fused QKV projection via tf32x3 tensor-core GEMM (round-7, passing)
// ---------------------------------------------------------------------------
__global__ void __launch_bounds__(256, 2)
qkv_mma_kernel(const float* __restrict__ leaves,
               const float* __restrict__ nodes,
               const float* __restrict__ Wq,
               const float* __restrict__ Wk,
               const float* __restrict__ Wv,
               const float* __restrict__ bq,
               const float* __restrict__ bk,
               const float* __restrict__ bv)
{
    const int z = blockIdx.z;
    const float* W    = (z == 0) ? Wq : (z == 1) ? Wk : Wv;
    const float* bias = (z == 0) ? bq : (z == 1) ? bk : bv;
    float* out        = (z == 0) ? g_q : (z == 1) ? g_k : g_v;
    const float scale = (z == 0) ? 0.125f : 1.0f;

    extern __shared__ uint32_t smem_u[];
    uint32_t* AH = smem_u;
    uint32_t* AL = AH + 128 * AST_;
    uint32_t* BH = AL + 128 * AST_;
    uint32_t* BL = BH + 64 * AST_;

    const int tid  = threadIdx.x;
    const int warp = tid >> 5;
    const int lane = tid & 31;
    const int g    = lane >> 2;
    const int tig  = lane & 3;
    const int warpM = warp & 3;
    const int warpN = warp >> 2;
    const int M0 = warpM * 32;
    const int N0 = warpN * 32;

    const int r0 = blockIdx.y * 128;
    const int c0 = blockIdx.x * 64;

    const int lm = tid >> 3;
    const int lk = (tid & 7) * 4;

    const float* xsrc[4];
    #pragma unroll
    for (int p = 0; p < 4; p++) {
        int gr = r0 + lm + p * 32;
        if (gr < ROWS_) {
            int b = gr / L_, t = gr % L_;
            xsrc[p] = (t < TK_) ? (leaves + ((size_t)(b * TK_ + t)) * D_)
                                : (nodes  + ((size_t)(b * NK_ + (t - TK_))) * D_);
        } else xsrc[p] = nullptr;
    }
    const float* wsrc0 = W + (size_t)(c0 + lm) * D_;
    const float* wsrc1 = W + (size_t)(c0 + lm + 32) * D_;

    float acc[2][4][4] = {};

    float4 xa[4], wb[2];
    #pragma unroll
    for (int p = 0; p < 4; p++) {
        xa[p] = make_float4(0.f, 0.f, 0.f, 0.f);
        if (xsrc[p]) xa[p] = *reinterpret_cast<const float4*>(xsrc[p] + lk);
    }
    wb[0] = *reinterpret_cast<const float4*>(wsrc0 + lk);
    wb[1] = *reinterpret_cast<const float4*>(wsrc1 + lk);

    for (int k0 = 0; k0 < D_; k0 += 32) {
        __syncthreads();
        #pragma unroll
        for (int p = 0; p < 4; p++) {
            uint4 h4, l4;
            split_tf32(xa[p].x, h4.x, l4.x);
            split_tf32(xa[p].y, h4.y, l4.y);
            split_tf32(xa[p].z, h4.z, l4.z);
            split_tf32(xa[p].w, h4.w, l4.w);
            int m = lm + p * 32;
            *reinterpret_cast<uint4*>(AH + m * AST_ + lk) = h4;
            *reinterpret_cast<uint4*>(AL + m * AST_ + lk) = l4;
        }
        #pragma unroll
        for (int p = 0; p < 2; p++) {
            uint4 h4, l4;
            split_tf32(wb[p].x, h4.x, l4.x);
            split_tf32(wb[p].y, h4.y, l4.y);
            split_tf32(wb[p].z, h4.z, l4.z);
            split_tf32(wb[p].w, h4.w, l4.w);
            int n = lm + p * 32;
            *reinterpret_cast<uint4*>(BH + n * AST_ + lk) = h4;
            *reinterpret_cast<uint4*>(BL + n * AST_ + lk) = l4;
        }
        __syncthreads();

        if (k0 + 32 < D_) {
            #pragma unroll
            for (int p = 0; p < 4; p++) {
                if (xsrc[p]) xa[p] = *reinterpret_cast<const float4*>(xsrc[p] + k0 + 32 + lk);
            }
            wb[0] = *reinterpret_cast<const float4*>(wsrc0 + k0 + 32 + lk);
            wb[1] = *reinterpret_cast<const float4*>(wsrc1 + k0 + 32 + lk);
        }

        #pragma unroll
        for (int ks = 0; ks < 4; ks++) {
            const int kk = ks * 8;
            uint32_t ah[2][4], al[2][4];
            #pragma unroll
            for (int mt = 0; mt < 2; mt++) {
                int rm = M0 + mt * 16;
                ah[mt][0] = AH[(rm + g) * AST_ + kk + tig];
                ah[mt][1] = AH[(rm + 8 + g) * AST_ + kk + tig];
                ah[mt][2] = AH[(rm + g) * AST_ + kk + tig + 4];
                ah[mt][3] = AH[(rm + 8 + g) * AST_ + kk + tig + 4];
                al[mt][0] = AL[(rm + g) * AST_ + kk + tig];
                al[mt][1] = AL[(rm + 8 + g) * AST_ + kk + tig];
                al[mt][2] = AL[(rm + g) * AST_ + kk + tig + 4];
                al[mt][3] = AL[(rm + 8 + g) * AST_ + kk + tig + 4];
            }
            uint32_t bh[4][2], bl[4][2];
            #pragma unroll
            for (int nt = 0; nt < 4; nt++) {
                int nb = N0 + nt * 8;
                bh[nt][0] = BH[(nb + g) * AST_ + kk + tig];
                bh[nt][1] = BH[(nb + g) * AST_ + kk + tig + 4];
                bl[nt][0] = BL[(nb + g) * AST_ + kk + tig];
                bl[nt][1] = BL[(nb + g) * AST_ + kk + tig + 4];
            }
            #pragma unroll
            for (int mt = 0; mt < 2; mt++)
                #pragma unroll
                for (int nt = 0; nt < 4; nt++) {
                    MMA_TF32(acc[mt][nt], ah[mt], bh[nt]);
                    MMA_TF32(acc[mt][nt], ah[mt], bl[nt]);
                    MMA_TF32(acc[mt][nt], al[mt], bh[nt]);
                }
        }
    }

    #pragma unroll
    for (int mt = 0; mt < 2; mt++)
        #pragma unroll
        for (int nt = 0; nt < 4; nt++) {
            int col = N0 + nt * 8 + tig * 2;
            int gc = c0 + col;
            int h = gc >> 6, d = gc & 63;
            float b0v = bias[gc], b1v = bias[gc + 1];
            #pragma unroll
            for (int hh = 0; hh < 2; hh++) {
                int gr = r0 + M0 + mt * 16 + g + hh * 8;
                if (gr >= ROWS_) continue;
                int b = gr / L_, l = gr % L_;
                float v0 = (acc[mt][nt][hh * 2 + 0] + b0v) * scale;
                float v1 = (acc[mt][nt][hh * 2 + 1] + b1v) * scale;
                float* dst = out + (((size_t)(b * H_ + h)) * L_ + l) * HD_ + d;
                dst[0] = v0;
                dst[1] = v1;
            }
        }
}

// ---------------------------------------------------------------------------
// Kernel 3: out = g_ao @ Wo^T + bo  (round-7, passing)
// ---------------------------------------------------------------------------
__global__ void __launch_bounds__(256, 2)
oproj_mma_kernel(const float* __restrict__ Wo,
                 const float* __restrict__ bo,
                 float* __restrict__ out)
{
    extern __shared__ uint32_t smem_u[];
    uint32_t* AH = smem_u;
    uint32_t* AL = AH + 128 * AST_;
    uint32_t* BH = AL + 128 * AST_;
    uint32_t* BL = BH + 64 * AST_;

    const int tid  = threadIdx.x;
    const int warp = tid >> 5;
    const int lane = tid & 31;
    const int g    = lane >> 2;
    const int tig  = lane & 3;
    const int warpM = warp & 3;
    const int warpN = warp >> 2;
    const int M0 = warpM * 32;
    const int N0 = warpN * 32;

    const int r0 = blockIdx.y * 128;
    const int c0 = blockIdx.x * 64;

    const int lm = tid >> 3;
    const int lk = (tid & 7) * 4;

    const float* xsrc[4];
    #pragma unroll
    for (int p = 0; p < 4; p++) {
        int gr = r0 + lm + p * 32;
        xsrc[p] = (gr < ROWS_) ? (g_ao + (size_t)gr * D_) : nullptr;
    }
    const float* wsrc0 = Wo + (size_t)(c0 + lm) * D_;
    const float* wsrc1 = Wo + (size_t)(c0 + lm + 32) * D_;

    float acc[2][4][4] = {};

    float4 xa[4], wb[2];
    #pragma unroll
    for (int p = 0; p < 4; p++) {
        xa[p] = make_float4(0.f, 0.f, 0.f, 0.f);
        if (xsrc[p]) xa[p] = *reinterpret_cast<const float4*>(xsrc[p] + lk);
    }
    wb[0] = *reinterpret_cast<const float4*>(wsrc0 + lk);
    wb[1] = *reinterpret_cast<const float4*>(wsrc1 + lk);

    for (int k0 = 0; k0 < D_; k0 += 32) {
        __syncthreads();
        #pragma unroll
        for (int p = 0; p < 4; p++) {
            uint4 h4, l4;
            split_tf32(xa[p].x, h4.x, l4.x);
            split_tf32(xa[p].y, h4.y, l4.y);
            split_tf32(xa[p].z, h4.z, l4.z);
            split_tf32(xa[p].w, h4.w, l4.w);
            int m = lm + p * 32;
            *reinterpret_cast<uint4*>(AH + m * AST_ + lk) = h4;
            *reinterpret_cast<uint4*>(AL + m * AST_ + lk) = l4;
        }
        #pragma unroll
        for (int p = 0; p < 2; p++) {
            uint4 h4, l4;
            split_tf32(wb[p].x, h4.x, l4.x);
            split_tf32(wb[p].y, h4.y, l4.y);
            split_tf32(wb[p].z, h4.z, l4.z);
            split_tf32(wb[p].w, h4.w, l4.w);
            int n = lm + p * 32;
            *reinterpret_cast<uint4*>(BH + n * AST_ + lk) = h4;
            *reinterpret_cast<uint4*>(BL + n * AST_ + lk) = l4;
        }
        __syncthreads();

        if (k0 + 32 < D_) {
            #pragma unroll
            for (int p = 0; p < 4; p++) {
                if (xsrc[p]) xa[p] = *reinterpret_cast<const float4*>(xsrc[p] + k0 + 32 + lk);
            }
            wb[0] = *reinterpret_cast<const float4*>(wsrc0 + k0 + 32 + lk);
            wb[1] = *reinterpret_cast<const float4*>(wsrc1 + k0 + 32 + lk);
        }

        #pragma unroll
        for (int ks = 0; ks < 4; ks++) {
            const int kk = ks * 8;
            uint32_t ah[2][4], al[2][4];
            #pragma unroll
            for (int mt = 0; mt < 2; mt++) {
                int rm = M0 + mt * 16;
                ah[mt][0] = AH[(rm + g) * AST_ + kk + tig];
                ah[mt][1] = AH[(rm + 8 + g) * AST_ + kk + tig];
                ah[mt][2] = AH[(rm + g) * AST_ + kk + tig + 4];
                ah[mt][3] = AH[(rm + 8 + g) * AST_ + kk + tig + 4];
                al[mt][0] = AL[(rm + g) * AST_ + kk + tig];
                al[mt][1] = AL[(rm + 8 + g) * AST_ + kk + tig];
                al[mt][2] = AL[(rm + g) * AST_ + kk + tig + 4];
                al[mt][3] = AL[(rm + 8 + g) * AST_ + kk + tig + 4];
            }
            uint32_t bh[4][2], bl[4][2];
            #pragma unroll
            for (int nt = 0; nt < 4; nt++) {
                int nb = N0 + nt * 8;
                bh[nt][0] = BH[(nb + g) * AST_ + kk + tig];
                bh[nt][1] = BH[(nb + g) * AST_ + kk + tig + 4];
                bl[nt][0] = BL[(nb + g) * AST_ + kk + tig];
                bl[nt][1] = BL[(nb + g) * AST_ + kk + tig + 4];
            }
            #pragma unroll
            for (int mt = 0; mt < 2; mt++)
                #pragma unroll
                for (int nt = 0; nt < 4; nt++) {
                    MMA_TF32(acc[mt][nt], ah[mt], bh[nt]);
                    MMA_TF32(acc[mt][nt], ah[mt], bl[nt]);
                    MMA_TF32(acc[mt][nt], al[mt], bh[nt]);
                }
        }
    }

    #pragma unroll
    for (int mt = 0; mt < 2; mt++)
        #pragma unroll
        for (int nt = 0; nt < 4; nt++) {
            int gc = c0 + N0 + nt * 8 + tig * 2;
            float b0v = bo[gc], b1v = bo[gc + 1];
            #pragma unroll
            for (int hh = 0; hh < 2; hh++) {
                int gr = r0 + M0 + mt * 16 + g + hh * 8;
                if (gr >= ROWS_) continue;
                float* dst = out + (size_t)gr * D_ + gc;
                dst[0] = acc[mt][nt][hh * 2 + 0] + b0v;
                dst[1] = acc[mt][nt][hh * 2 + 1] + b1v;
            }
        }
}

// ---------------------------------------------------------------------------
// Kernel 2: flash attention (tf32x3 mma) with PERM-K smem layout, stride 68.
// perm within each 8-k group: k<4 -> 2k ; k>=4 -> 2(k-4)+1, so every mma
// fragment pair (k=tig, k=tig+4) is a contiguous uint2.
// K: [j][perm k]; V transposed: [d][perm j]; P/Q staged: [i][perm k/j].
// ---------------------------------------------------------------------------
__global__ void flash_mma_kernel(const int* __restrict__ node_indices,
                                 const unsigned char* __restrict__ key_pad,
                                 const unsigned char* __restrict__ node_pad)
{
    extern __shared__ uint32_t sm[];
    uint32_t* KH = sm;
    uint32_t* KL = KH + 64 * FST_;
    uint32_t* VH = KL + 64 * FST_;
    uint32_t* VL = VH + 64 * FST_;
    uint32_t* PH = VL + 64 * FST_;
    uint32_t* PL = PH + 64 * FST_;
    int* clo = (int*)(PL + 64 * FST_);
    int* chi = clo + 64;

    const int bh = blockIdx.y;
    const int b  = bh >> 3;
    const int h  = bh & 7;
    const int i0 = (15 - (int)blockIdx.x) * 64;   // heavy (node) blocks first
    const bool qleaf = (i0 < TK_);

    const int tid  = threadIdx.x;       // 128
    const int warp = tid >> 5;
    const int lane = tid & 31;
    const int g    = lane >> 2;
    const int tig  = lane & 3;
    const int wrow = warp * 16;

    const int lj  = tid >> 4;           // 0..7
    const int lk4 = (tid & 15) * 4;     // 0,4,...,60
    const int pbase = (lk4 & ~7) + ((lk4 & 4) ? 1 : 0);   // perm base, stride 2

    // ---- stage Q into PH/PL (perm-k), then lift fragments to registers ----
    #pragma unroll
    for (int p = 0; p < 8; p++) {
        int row = p * 8 + lj;
        int gi = i0 + row;
        float4 qv = make_float4(0.f, 0.f, 0.f, 0.f);
        if (gi < L_)
            qv = *reinterpret_cast<const float4*>(g_q + ((size_t)bh * L_ + gi) * HD_ + lk4);
        uint32_t hx, lx;
        int base = row * FST_ + pbase;
        split_tf32(qv.x, hx, lx); PH[base + 0] = hx; PL[base + 0] = lx;
        split_tf32(qv.y, hx, lx); PH[base + 2] = hx; PL[base + 2] = lx;
        split_tf32(qv.z, hx, lx); PH[base + 4] = hx; PL[base + 4] = lx;
        split_tf32(qv.w, hx, lx); PH[base + 6] = hx; PL[base + 6] = lx;
    }
    __syncthreads();

    uint32_t qh[8][4], ql[8][4];
    #pragma unroll
    for (int kk = 0; kk < 8; kk++) {
        uint2 t0 = *reinterpret_cast<uint2*>(&PH[(wrow + g) * FST_ + kk * 8 + 2 * tig]);
        uint2 t1 = *reinterpret_cast<uint2*>(&PH[(wrow + 8 + g) * FST_ + kk * 8 + 2 * tig]);
        qh[kk][0] = t0.x; qh[kk][1] = t1.x; qh[kk][2] = t0.y; qh[kk][3] = t1.y;
        uint2 u0 = *reinterpret_cast<uint2*>(&PL[(wrow + g) * FST_ + kk * 8 + 2 * tig]);
        uint2 u1 = *reinterpret_cast<uint2*>(&PL[(wrow + 8 + g) * FST_ + kk * 8 + 2 * tig]);
        ql[kk][0] = u0.x; ql[kk][1] = u1.x; ql[kk][2] = u0.y; ql[kk][3] = u1.y;
    }

    // ---- per-row mask params (rows r0 via c0/c1, r1 via c2/c3) ----
    const int r0 = i0 + wrow + g;
    const int r1 = r0 + 8;
    int qlo0 = 0, qhi0 = 0, qloL0 = 0, qlo1 = 0, qhi1 = 0, qloL1 = 0;
    if (!qleaf) {
        int nq0 = min(r0 - TK_, NK_ - 1);
        qlo0 = node_indices[((size_t)bh * NK_ + nq0) * 2 + 0];
        qhi0 = node_indices[((size_t)bh * NK_ + nq0) * 2 + 1];
        qloL0 = (node_pad[b * NK_ + nq0] != 0) ? (1 << 28) : qlo0;
        int nq1 = min(r1 - TK_, NK_ - 1);
        qlo1 = node_indices[((size_t)bh * NK_ + nq1) * 2 + 0];
        qhi1 = node_indices[((size_t)bh * NK_ + nq1) * 2 + 1];
        qloL1 = (node_pad[b * NK_ + nq1] != 0) ? (1 << 28) : qlo1;
    }

    float m0 = -1e30f, m1 = -1e30f, lsum0 = 0.f, lsum1 = 0.f;
    float acc[8][4] = {};

    const int ntiles = qleaf ? 8 : (9 + (i0 - TK_) / 64);
    for (int jt = 0; jt < ntiles; jt++) {
        const bool nodetile = (jt >= 8);
        const int j0 = nodetile ? TK_ + (jt - 8) * 64 : jt * 64;

        __syncthreads();
        // ---- K tile: rows j, perm k ----
        #pragma unroll
        for (int p = 0; p < 8; p++) {
            int row = p * 8 + lj;
            int gj = j0 + row;
            float4 kv = make_float4(0.f, 0.f, 0.f, 0.f);
            if (gj < L_)
                kv = *reinterpret_cast<const float4*>(g_k + ((size_t)bh * L_ + gj) * HD_ + lk4);
            uint32_t hx, lx;
            int base = row * FST_ + pbase;
            split_tf32(kv.x, hx, lx); KH[base + 0] = hx; KL[base + 0] = lx;
            split_tf32(kv.y, hx, lx); KH[base + 2] = hx; KL[base + 2] = lx;
            split_tf32(kv.z, hx, lx); KH[base + 4] = hx; KL[base + 4] = lx;
            split_tf32(kv.w, hx, lx); KH[base + 6] = hx; KL[base + 6] = lx;
        }
        // ---- V tile transposed: rows d, perm k = j ----
        #pragma unroll
        for (int p = 0; p < 8; p++) {
            int row = p * 8 + lj;        // source j within tile
            int gj = j0 + row;
            float4 vv = make_float4(0.f, 0.f, 0.f, 0.f);
            if (gj < L_)
                vv = *reinterpret_cast<const float4*>(g_v + ((size_t)bh * L_ + gj) * HD_ + lk4);
            int w8 = row & 7;
            int pj = (row & ~7) + ((w8 < 4) ? 2 * w8 : 2 * (w8 - 4) + 1);
            uint32_t hx, lx;
            split_tf32(vv.x, hx, lx); VH[(lk4 + 0) * FST_ + pj] = hx; VL[(lk4 + 0) * FST_ + pj] = lx;
            split_tf32(vv.y, hx, lx); VH[(lk4 + 1) * FST_ + pj] = hx; VL[(lk4 + 1) * FST_ + pj] = lx;
            split_tf32(vv.z, hx, lx); VH[(lk4 + 2) * FST_ + pj] = hx; VL[(lk4 + 2) * FST_ + pj] = lx;
            split_tf32(vv.w, hx, lx); VH[(lk4 + 3) * FST_ + pj] = hx; VL[(lk4 + 3) * FST_ + pj] = lx;
        }
        // ---- node-key column metadata ----
        if (nodetile && tid < 64) {
            int gj = j0 + tid;
            int nj = gj - TK_;
            int lo = (1 << 28), hi = -(1 << 28);
            if (nj < NK_ && gj < L_ && node_pad[b * NK_ + nj] == 0) {
                lo = node_indices[((size_t)bh * NK_ + nj) * 2 + 0];
                hi = node_indices[((size_t)bh * NK_ + nj) * 2 + 1];
            }
            clo[tid] = lo;
            chi[tid] = hi;
        }
        __syncthreads();

        // ---- S = Q K^T ----
        float s[8][4];
        #pragma unroll
        for (int nf = 0; nf < 8; nf++) {
            s[nf][0] = 0.f; s[nf][1] = 0.f; s[nf][2] = 0.f; s[nf][3] = 0.f;
        }
        for (int kk = 0; kk < 8; kk++) {
            #pragma unroll
            for (int nf = 0; nf < 8; nf++) {
                uint2 bh2 = *reinterpret_cast<uint2*>(&KH[(nf * 8 + g) * FST_ + kk * 8 + 2 * tig]);
                uint2 bl2 = *reinterpret_cast<uint2*>(&KL[(nf * 8 + g) * FST_ + kk * 8 + 2 * tig]);
                uint32_t bhv[2] = {bh2.x, bh2.y};
                uint32_t blv[2] = {bl2.x, bl2.y};
                MMA_TF32(s[nf], qh[kk], bhv);
                MMA_TF32(s[nf], qh[kk], blv);
                MMA_TF32(s[nf], ql[kk], bhv);
            }
        }

        // ---- mask ----
        if (qleaf) {
            #pragma unroll
            for (int nf = 0; nf < 8; nf++) {
                int gj = j0 + nf * 8 + 2 * tig;
                if (key_pad[b * TK_ + gj])     { s[nf][0] = -1e30f; s[nf][2] = -1e30f; }
                if (key_pad[b * TK_ + gj + 1]) { s[nf][1] = -1e30f; s[nf][3] = -1e30f; }
            }
        } else if (!nodetile) {
            #pragma unroll
            for (int nf = 0; nf < 8; nf++) {
                int gj = j0 + nf * 8 + 2 * tig;
                bool kp0 = (key_pad[b * TK_ + gj] != 0);
                bool kp1 = (key_pad[b * TK_ + gj + 1] != 0);
                if (!(gj >= qloL0 && gj <= qhi0 && !kp0))             s[nf][0] = -1e30f;
                if (!((gj + 1) >= qloL0 && (gj + 1) <= qhi0 && !kp1)) s[nf][1] = -1e30f;
                if (!(gj >= qloL1 && gj <= qhi1 && !kp0))             s[nf][2] = -1e30f;
                if (!((gj + 1) >= qloL1 && (gj + 1) <= qhi1 && !kp1)) s[nf][3] = -1e30f;
            }
        } else {
            int nq0 = r0 - TK_, nq1 = r1 - TK_;
            #pragma unroll
            for (int nf = 0; nf < 8; nf++) {
                int cj = nf * 8 + 2 * tig;
                int nj0 = j0 + cj - TK_;
                int lo20 = clo[cj],     hi20 = chi[cj];
                int lo21 = clo[cj + 1], hi21 = chi[cj + 1];
                if (!(nj0 <= nq0 && max(qlo0, lo20) <= min(qhi0, hi20)))     s[nf][0] = -1e30f;
                if (!(nj0 + 1 <= nq0 && max(qlo0, lo21) <= min(qhi0, hi21))) s[nf][1] = -1e30f;
                if (!(nj0 <= nq1 && max(qlo1, lo20) <= min(qhi1, hi20)))     s[nf][2] = -1e30f;
                if (!(nj0 + 1 <= nq1 && max(qlo1, lo21) <= min(qhi1, hi21))) s[nf][3] = -1e30f;
            }
        }

        // ---- online softmax ----
        float tm0 = -1e30f, tm1 = -1e30f;
        #pragma unroll
        for (int nf = 0; nf < 8; nf++) {
            tm0 = fmaxf(tm0, fmaxf(s[nf][0], s[nf][1]));
            tm1 = fmaxf(tm1, fmaxf(s[nf][2], s[nf][3]));
        }
        tm0 = fmaxf(tm0, __shfl_xor_sync(0xffffffffu, tm0, 1));
        tm0 = fmaxf(tm0, __shfl_xor_sync(0xffffffffu, tm0, 2));
        tm1 = fmaxf(tm1, __shfl_xor_sync(0xffffffffu, tm1, 1));
        tm1 = fmaxf(tm1, __shfl_xor_sync(0xffffffffu, tm1, 2));

        float mn0 = fmaxf(m0, tm0);
        float mn1 = fmaxf(m1, tm1);
        float a0 = __expf(m0 - mn0);
        float a1 = __expf(m1 - mn1);
        m0 = mn0; m1 = mn1;
        float sb0 = fmaxf(mn0, -1e20f);
        float sb1 = fmaxf(mn1, -1e20f);

        float rs0 = 0.f, rs1 = 0.f;
        #pragma unroll
        for (int nf = 0; nf < 8; nf++) {
            s[nf][0] = __expf(s[nf][0] - sb0);
            s[nf][1] = __expf(s[nf][1] - sb0);
            s[nf][2] = __expf(s[nf][2] - sb1);
            s[nf][3] = __expf(s[nf][3] - sb1);
            rs0 += s[nf][0] + s[nf][1];
            rs1 += s[nf][2] + s[nf][3];
        }
        rs0 += __shfl_xor_sync(0xffffffffu, rs0, 1);
        rs0 += __shfl_xor_sync(0xffffffffu, rs0, 2);
        rs1 += __shfl_xor_sync(0xffffffffu, rs1, 1);
        rs1 += __shfl_xor_sync(0xffffffffu, rs1, 2);
        lsum0 = lsum0 * a0 + rs0;
        lsum1 = lsum1 * a1 + rs1;
        #pragma unroll
        for (int nf = 0; nf < 8; nf++) {
            acc[nf][0] *= a0; acc[nf][1] *= a0;
            acc[nf][2] *= a1; acc[nf][3] *= a1;
        }

        // ---- write P (perm-k layout) hi/lo ----
        const int ph0 = (tig < 2) ? 4 * tig : 4 * tig - 7;
        #pragma unroll
        for (int nf = 0; nf < 8; nf++) {
            int bg  = (wrow + g) * FST_ + nf * 8 + ph0;
            int bg8 = (wrow + 8 + g) * FST_ + nf * 8 + ph0;
            uint32_t hx, lx;
            split_tf32(s[nf][0], hx, lx); PH[bg] = hx;      PL[bg] = lx;
            split_tf32(s[nf][1], hx, lx); PH[bg + 2] = hx;  PL[bg + 2] = lx;
            split_tf32(s[nf][2], hx, lx); PH[bg8] = hx;     PL[bg8] = lx;
            split_tf32(s[nf][3], hx, lx); PH[bg8 + 2] = hx; PL[bg8 + 2] = lx;
        }
        __syncwarp();

        // ---- acc += P V ----
        for (int kk = 0; kk < 8; kk++) {
            uint2 t0 = *reinterpret_cast<uint2*>(&PH[(wrow + g) * FST_ + kk * 8 + 2 * tig]);
            uint2 t1 = *reinterpret_cast<uint2*>(&PH[(wrow + 8 + g) * FST_ + kk * 8 + 2 * tig]);
            uint32_t ah[4] = {t0.x, t1.x, t0.y, t1.y};
            uint2 u0 = *reinterpret_cast<uint2*>(&PL[(wrow + g) * FST_ + kk * 8 + 2 * tig]);
            uint2 u1 = *reinterpret_cast<uint2*>(&PL[(wrow + 8 + g) * FST_ + kk * 8 + 2 * tig]);
            uint32_t al[4] = {u0.x, u1.x, u0.y, u1.y};
            #pragma unroll
            for (int nf = 0; nf < 8; nf++) {
                uint2 bh2 = *reinterpret_cast<uint2*>(&VH[(nf * 8 + g) * FST_ + kk * 8 + 2 * tig]);
                uint2 bl2 = *reinterpret_cast<uint2*>(&VL[(nf * 8 + g) * FST_ + kk * 8 + 2 * tig]);
                uint32_t bhv[2] = {bh2.x, bh2.y};
                uint32_t blv[2] = {bl2.x, bl2.y};
                MMA_TF32(acc[nf], ah, bhv);
                MMA_TF32(acc[nf], ah, blv);
                MMA_TF32(acc[nf], al, bhv);
            }
        }
    }

    // ---- epilogue ----
    float inv0 = 1.0f / lsum0;
    float inv1 = 1.0f / lsum1;
    #pragma unroll
    for (int nf = 0; nf < 8; nf++) {
        int d0 = nf * 8 + 2 * tig;
        if (r0 < L_) {
            float2 v = make_float2(acc[nf][0] * inv0, acc[nf][1] * inv0);
            *reinterpret_cast<float2*>(g_ao + ((size_t)(b * L_ + r0)) * D_ + h * HD_ + d0) = v;
        }
        if (r1 < L_) {
            float2 v = make_float2(acc[nf][2] * inv1, acc[nf][3] * inv1);
            *reinterpret_cast<float2*>(g_ao + ((size_t)(b * L_ + r1)) * D_ + h * HD_ + d0) = v;
        }
    }
}

// ---------------------------------------------------------------------------
extern "C" void kernel_launch(void* const* d_in, const int* in_sizes, int n_in,
                              void* d_out, int out_size)
{
    const float* leaves = (const float*)d_in[0];
    const float* nodes  = (const float*)d_in[1];
    const float* Wq     = (const float*)d_in[2];
    const float* Wk     = (const float*)d_in[3];
    const float* Wv     = (const float*)d_in[4];
    const float* Wo     = (const float*)d_in[5];
    const float* bq     = (const float*)d_in[6];
    const float* bk     = (const float*)d_in[7];
    const float* bv     = (const float*)d_in[8];
    const float* bo     = (const float*)d_in[9];
    const int*   node_indices = (const int*)d_in[10];
    const unsigned char* key_pad  = (const unsigned char*)d_in[11];
    const unsigned char* node_pad = (const unsigned char*)d_in[12];
    float* out = (float*)d_out;

    static int smem_set = 0;
    if (!smem_set) {
        cudaFuncSetAttribute(flash_mma_kernel,
                             cudaFuncAttributeMaxDynamicSharedMemorySize,
                             FLASH_SMEM);
        cudaFuncSetAttribute(qkv_mma_kernel,
                             cudaFuncAttributeMaxDynamicSharedMemorySize,
                             GEMM_SMEM_BYTES);
        cudaFuncSetAttribute(oproj_mma_kernel,
                             cudaFuncAttributeMaxDynamicSharedMemorySize,
                             GEMM_SMEM_BYTES);
        smem_set = 1;
    }

    qkv_mma_kernel<<<dim3(8, 32, 3), 256, GEMM_SMEM_BYTES>>>(
        leaves, nodes, Wq, Wk, Wv, bq, bk, bv);
    flash_mma_kernel<<<dim3(16, 32), 128, FLASH_SMEM>>>(node_indices, key_pad, node_pad);
    oproj_mma_kernel<<<dim3(8, 32), 256, GEMM_SMEM_BYTES>>>(Wo, bo, out);
}

// round 10
// speedup vs baseline: 1.1374x; 1.1374x over previous
#include <cuda_runtime.h>
#include <cstdint>

#define B_    4
#define H_    8
#define TK_   512
#define NK_   511
#define L_    1023
#define D_    512
#define HD_   64
#define BH_   32
#define ROWS_ 4092          // B_*L_

// Scratch (static __device__ — no allocations allowed)
__device__ float g_q[B_*H_*L_*HD_];
__device__ float g_k[B_*H_*L_*HD_];
__device__ float g_v[B_*H_*L_*HD_];
__device__ float g_ao[B_*L_*D_];            // attention output, (B,L, H*HD)

// ---------------------------------------------------------------------------
// tf32 helpers
// ---------------------------------------------------------------------------
__device__ __forceinline__ void split_tf32(float x, uint32_t& hi, uint32_t& lo)
{
    float h, l2;
    asm("cvt.rna.tf32.f32 %0, %1;" : "=f"(h) : "f"(x));
    float l = x - h;
    asm("cvt.rna.tf32.f32 %0, %1;" : "=f"(l2) : "f"(l));
    hi = __float_as_uint(h);
    lo = __float_as_uint(l2);
}

#define MMA_TF32(d, a, b)                                                     \
    asm volatile(                                                             \
        "mma.sync.aligned.m16n8k8.row.col.f32.tf32.tf32.f32 "                 \
        "{%0,%1,%2,%3}, {%4,%5,%6,%7}, {%8,%9}, {%0,%1,%2,%3};"               \
        : "+f"((d)[0]), "+f"((d)[1]), "+f"((d)[2]), "+f"((d)[3])              \
        : "r"((a)[0]), "r"((a)[1]), "r"((a)[2]), "r"((a)[3]),                 \
          "r"((b)[0]), "r"((b)[1]))

// GEMM kernels: k-chunk = 32 -> stride 36
#define AST_ 36
#define GEMM_SMEM_BYTES ((2*128*AST_ + 2*64*AST_) * 4)   // 55296
// Flash: 4 tile buffers (K hi/lo + V hi/lo); P reuses the K buffer.
#define FST_ 68
#define FLASH_SMEM (4*64*FST_*4 + 2*64*4)                // 70144

// ---------------------------------------------------------------------------
// Kernel 1: fused QKV projection via tf32x3 tensor-core GEMM (round-7, passing)
// ---------------------------------------------------------------------------
__global__ void __launch_bounds__(256, 2)
qkv_mma_kernel(const float* __restrict__ leaves,
               const float* __restrict__ nodes,
               const float* __restrict__ Wq,
               const float* __restrict__ Wk,
               const float* __restrict__ Wv,
               const float* __restrict__ bq,
               const float* __restrict__ bk,
               const float* __restrict__ bv)
{
    const int z = blockIdx.z;
    const float* W    = (z == 0) ? Wq : (z == 1) ? Wk : Wv;
    const float* bias = (z == 0) ? bq : (z == 1) ? bk : bv;
    float* out        = (z == 0) ? g_q : (z == 1) ? g_k : g_v;
    const float scale = (z == 0) ? 0.125f : 1.0f;

    extern __shared__ uint32_t smem_u[];
    uint32_t* AH = smem_u;
    uint32_t* AL = AH + 128 * AST_;
    uint32_t* BH = AL + 128 * AST_;
    uint32_t* BL = BH + 64 * AST_;

    const int tid  = threadIdx.x;
    const int warp = tid >> 5;
    const int lane = tid & 31;
    const int g    = lane >> 2;
    const int tig  = lane & 3;
    const int warpM = warp & 3;
    const int warpN = warp >> 2;
    const int M0 = warpM * 32;
    const int N0 = warpN * 32;

    const int r0 = blockIdx.y * 128;
    const int c0 = blockIdx.x * 64;

    const int lm = tid >> 3;
    const int lk = (tid & 7) * 4;

    const float* xsrc[4];
    #pragma unroll
    for (int p = 0; p < 4; p++) {
        int gr = r0 + lm + p * 32;
        if (gr < ROWS_) {
            int b = gr / L_, t = gr % L_;
            xsrc[p] = (t < TK_) ? (leaves + ((size_t)(b * TK_ + t)) * D_)
                                : (nodes  + ((size_t)(b * NK_ + (t - TK_))) * D_);
        } else xsrc[p] = nullptr;
    }
    const float* wsrc0 = W + (size_t)(c0 + lm) * D_;
    const float* wsrc1 = W + (size_t)(c0 + lm + 32) * D_;

    float acc[2][4][4] = {};

    float4 xa[4], wb[2];
    #pragma unroll
    for (int p = 0; p < 4; p++) {
        xa[p] = make_float4(0.f, 0.f, 0.f, 0.f);
        if (xsrc[p]) xa[p] = *reinterpret_cast<const float4*>(xsrc[p] + lk);
    }
    wb[0] = *reinterpret_cast<const float4*>(wsrc0 + lk);
    wb[1] = *reinterpret_cast<const float4*>(wsrc1 + lk);

    for (int k0 = 0; k0 < D_; k0 += 32) {
        __syncthreads();
        #pragma unroll
        for (int p = 0; p < 4; p++) {
            uint4 h4, l4;
            split_tf32(xa[p].x, h4.x, l4.x);
            split_tf32(xa[p].y, h4.y, l4.y);
            split_tf32(xa[p].z, h4.z, l4.z);
            split_tf32(xa[p].w, h4.w, l4.w);
            int m = lm + p * 32;
            *reinterpret_cast<uint4*>(AH + m * AST_ + lk) = h4;
            *reinterpret_cast<uint4*>(AL + m * AST_ + lk) = l4;
        }
        #pragma unroll
        for (int p = 0; p < 2; p++) {
            uint4 h4, l4;
            split_tf32(wb[p].x, h4.x, l4.x);
            split_tf32(wb[p].y, h4.y, l4.y);
            split_tf32(wb[p].z, h4.z, l4.z);
            split_tf32(wb[p].w, h4.w, l4.w);
            int n = lm + p * 32;
            *reinterpret_cast<uint4*>(BH + n * AST_ + lk) = h4;
            *reinterpret_cast<uint4*>(BL + n * AST_ + lk) = l4;
        }
        __syncthreads();

        if (k0 + 32 < D_) {
            #pragma unroll
            for (int p = 0; p < 4; p++) {
                if (xsrc[p]) xa[p] = *reinterpret_cast<const float4*>(xsrc[p] + k0 + 32 + lk);
            }
            wb[0] = *reinterpret_cast<const float4*>(wsrc0 + k0 + 32 + lk);
            wb[1] = *reinterpret_cast<const float4*>(wsrc1 + k0 + 32 + lk);
        }

        #pragma unroll
        for (int ks = 0; ks < 4; ks++) {
            const int kk = ks * 8;
            uint32_t ah[2][4], al[2][4];
            #pragma unroll
            for (int mt = 0; mt < 2; mt++) {
                int rm = M0 + mt * 16;
                ah[mt][0] = AH[(rm + g) * AST_ + kk + tig];
                ah[mt][1] = AH[(rm + 8 + g) * AST_ + kk + tig];
                ah[mt][2] = AH[(rm + g) * AST_ + kk + tig + 4];
                ah[mt][3] = AH[(rm + 8 + g) * AST_ + kk + tig + 4];
                al[mt][0] = AL[(rm + g) * AST_ + kk + tig];
                al[mt][1] = AL[(rm + 8 + g) * AST_ + kk + tig];
                al[mt][2] = AL[(rm + g) * AST_ + kk + tig + 4];
                al[mt][3] = AL[(rm + 8 + g) * AST_ + kk + tig + 4];
            }
            uint32_t bh[4][2], bl[4][2];
            #pragma unroll
            for (int nt = 0; nt < 4; nt++) {
                int nb = N0 + nt * 8;
                bh[nt][0] = BH[(nb + g) * AST_ + kk + tig];
                bh[nt][1] = BH[(nb + g) * AST_ + kk + tig + 4];
                bl[nt][0] = BL[(nb + g) * AST_ + kk + tig];
                bl[nt][1] = BL[(nb + g) * AST_ + kk + tig + 4];
            }
            #pragma unroll
            for (int mt = 0; mt < 2; mt++)
                #pragma unroll
                for (int nt = 0; nt < 4; nt++) {
                    MMA_TF32(acc[mt][nt], ah[mt], bh[nt]);
                    MMA_TF32(acc[mt][nt], ah[mt], bl[nt]);
                    MMA_TF32(acc[mt][nt], al[mt], bh[nt]);
                }
        }
    }

    #pragma unroll
    for (int mt = 0; mt < 2; mt++)
        #pragma unroll
        for (int nt = 0; nt < 4; nt++) {
            int col = N0 + nt * 8 + tig * 2;
            int gc = c0 + col;
            int h = gc >> 6, d = gc & 63;
            float b0v = bias[gc], b1v = bias[gc + 1];
            #pragma unroll
            for (int hh = 0; hh < 2; hh++) {
                int gr = r0 + M0 + mt * 16 + g + hh * 8;
                if (gr >= ROWS_) continue;
                int b = gr / L_, l = gr % L_;
                float v0 = (acc[mt][nt][hh * 2 + 0] + b0v) * scale;
                float v1 = (acc[mt][nt][hh * 2 + 1] + b1v) * scale;
                float* dst = out + (((size_t)(b * H_ + h)) * L_ + l) * HD_ + d;
                dst[0] = v0;
                dst[1] = v1;
            }
        }
}

// ---------------------------------------------------------------------------
// Kernel 3: out = g_ao @ Wo^T + bo  (round-7, passing)
// ---------------------------------------------------------------------------
__global__ void __launch_bounds__(256, 2)
oproj_mma_kernel(const float* __restrict__ Wo,
                 const float* __restrict__ bo,
                 float* __restrict__ out)
{
    extern __shared__ uint32_t smem_u[];
    uint32_t* AH = smem_u;
    uint32_t* AL = AH + 128 * AST_;
    uint32_t* BH = AL + 128 * AST_;
    uint32_t* BL = BH + 64 * AST_;

    const int tid  = threadIdx.x;
    const int warp = tid >> 5;
    const int lane = tid & 31;
    const int g    = lane >> 2;
    const int tig  = lane & 3;
    const int warpM = warp & 3;
    const int warpN = warp >> 2;
    const int M0 = warpM * 32;
    const int N0 = warpN * 32;

    const int r0 = blockIdx.y * 128;
    const int c0 = blockIdx.x * 64;

    const int lm = tid >> 3;
    const int lk = (tid & 7) * 4;

    const float* xsrc[4];
    #pragma unroll
    for (int p = 0; p < 4; p++) {
        int gr = r0 + lm + p * 32;
        xsrc[p] = (gr < ROWS_) ? (g_ao + (size_t)gr * D_) : nullptr;
    }
    const float* wsrc0 = Wo + (size_t)(c0 + lm) * D_;
    const float* wsrc1 = Wo + (size_t)(c0 + lm + 32) * D_;

    float acc[2][4][4] = {};

    float4 xa[4], wb[2];
    #pragma unroll
    for (int p = 0; p < 4; p++) {
        xa[p] = make_float4(0.f, 0.f, 0.f, 0.f);
        if (xsrc[p]) xa[p] = *reinterpret_cast<const float4*>(xsrc[p] + lk);
    }
    wb[0] = *reinterpret_cast<const float4*>(wsrc0 + lk);
    wb[1] = *reinterpret_cast<const float4*>(wsrc1 + lk);

    for (int k0 = 0; k0 < D_; k0 += 32) {
        __syncthreads();
        #pragma unroll
        for (int p = 0; p < 4; p++) {
            uint4 h4, l4;
            split_tf32(xa[p].x, h4.x, l4.x);
            split_tf32(xa[p].y, h4.y, l4.y);
            split_tf32(xa[p].z, h4.z, l4.z);
            split_tf32(xa[p].w, h4.w, l4.w);
            int m = lm + p * 32;
            *reinterpret_cast<uint4*>(AH + m * AST_ + lk) = h4;
            *reinterpret_cast<uint4*>(AL + m * AST_ + lk) = l4;
        }
        #pragma unroll
        for (int p = 0; p < 2; p++) {
            uint4 h4, l4;
            split_tf32(wb[p].x, h4.x, l4.x);
            split_tf32(wb[p].y, h4.y, l4.y);
            split_tf32(wb[p].z, h4.z, l4.z);
            split_tf32(wb[p].w, h4.w, l4.w);
            int n = lm + p * 32;
            *reinterpret_cast<uint4*>(BH + n * AST_ + lk) = h4;
            *reinterpret_cast<uint4*>(BL + n * AST_ + lk) = l4;
        }
        __syncthreads();

        if (k0 + 32 < D_) {
            #pragma unroll
            for (int p = 0; p < 4; p++) {
                if (xsrc[p]) xa[p] = *reinterpret_cast<const float4*>(xsrc[p] + k0 + 32 + lk);
            }
            wb[0] = *reinterpret_cast<const float4*>(wsrc0 + k0 + 32 + lk);
            wb[1] = *reinterpret_cast<const float4*>(wsrc1 + k0 + 32 + lk);
        }

        #pragma unroll
        for (int ks = 0; ks < 4; ks++) {
            const int kk = ks * 8;
            uint32_t ah[2][4], al[2][4];
            #pragma unroll
            for (int mt = 0; mt < 2; mt++) {
                int rm = M0 + mt * 16;
                ah[mt][0] = AH[(rm + g) * AST_ + kk + tig];
                ah[mt][1] = AH[(rm + 8 + g) * AST_ + kk + tig];
                ah[mt][2] = AH[(rm + g) * AST_ + kk + tig + 4];
                ah[mt][3] = AH[(rm + 8 + g) * AST_ + kk + tig + 4];
                al[mt][0] = AL[(rm + g) * AST_ + kk + tig];
                al[mt][1] = AL[(rm + 8 + g) * AST_ + kk + tig];
                al[mt][2] = AL[(rm + g) * AST_ + kk + tig + 4];
                al[mt][3] = AL[(rm + 8 + g) * AST_ + kk + tig + 4];
            }
            uint32_t bh[4][2], bl[4][2];
            #pragma unroll
            for (int nt = 0; nt < 4; nt++) {
                int nb = N0 + nt * 8;
                bh[nt][0] = BH[(nb + g) * AST_ + kk + tig];
                bh[nt][1] = BH[(nb + g) * AST_ + kk + tig + 4];
                bl[nt][0] = BL[(nb + g) * AST_ + kk + tig];
                bl[nt][1] = BL[(nb + g) * AST_ + kk + tig + 4];
            }
            #pragma unroll
            for (int mt = 0; mt < 2; mt++)
                #pragma unroll
                for (int nt = 0; nt < 4; nt++) {
                    MMA_TF32(acc[mt][nt], ah[mt], bh[nt]);
                    MMA_TF32(acc[mt][nt], ah[mt], bl[nt]);
                    MMA_TF32(acc[mt][nt], al[mt], bh[nt]);
                }
        }
    }

    #pragma unroll
    for (int mt = 0; mt < 2; mt++)
        #pragma unroll
        for (int nt = 0; nt < 4; nt++) {
            int gc = c0 + N0 + nt * 8 + tig * 2;
            float b0v = bo[gc], b1v = bo[gc + 1];
            #pragma unroll
            for (int hh = 0; hh < 2; hh++) {
                int gr = r0 + M0 + mt * 16 + g + hh * 8;
                if (gr >= ROWS_) continue;
                float* dst = out + (size_t)gr * D_ + gc;
                dst[0] = acc[mt][nt][hh * 2 + 0] + b0v;
                dst[1] = acc[mt][nt][hh * 2 + 1] + b1v;
            }
        }
}

// ---------------------------------------------------------------------------
// Kernel 2: flash attention (tf32x3, round-7 plain layout) with P sharing the
// K buffer -> smem 70KB -> 3 CTAs/SM. Q stages through the V buffer.
// ---------------------------------------------------------------------------
__global__ void __launch_bounds__(128, 3)
flash_mma_kernel(const int* __restrict__ node_indices,
                 const unsigned char* __restrict__ key_pad,
                 const unsigned char* __restrict__ node_pad)
{
    extern __shared__ uint32_t sm[];
    uint32_t* KH = sm;                   // K tile, then P tile (hi)
    uint32_t* KL = KH + 64 * FST_;       // K tile, then P tile (lo)
    uint32_t* VH = KL + 64 * FST_;       // V tile (hi); Q staging pre-loop
    uint32_t* VL = VH + 64 * FST_;       // V tile (lo)
    int* clo = (int*)(VL + 64 * FST_);
    int* chi = clo + 64;

    const int bh = blockIdx.y;
    const int b  = bh >> 3;
    const int h  = bh & 7;
    const int i0 = (15 - (int)blockIdx.x) * 64;   // heavy (node) blocks first
    const bool qleaf = (i0 < TK_);

    const int tid  = threadIdx.x;       // 128
    const int warp = tid >> 5;
    const int lane = tid & 31;
    const int g    = lane >> 2;
    const int tig  = lane & 3;
    const int wrow = warp * 16;

    const int lj = tid >> 4;            // 0..7
    const int lc = (tid & 15) * 4;      // 0,4,...,60

    // ---- stage Q into VH/VL (plain [i][k], stride 68) ----
    #pragma unroll
    for (int p = 0; p < 8; p++) {
        int row = p * 8 + lj;
        int gi = i0 + row;
        float4 qv = make_float4(0.f, 0.f, 0.f, 0.f);
        if (gi < L_)
            qv = *reinterpret_cast<const float4*>(g_q + ((size_t)bh * L_ + gi) * HD_ + lc);
        uint4 h4, l4;
        split_tf32(qv.x, h4.x, l4.x);
        split_tf32(qv.y, h4.y, l4.y);
        split_tf32(qv.z, h4.z, l4.z);
        split_tf32(qv.w, h4.w, l4.w);
        *reinterpret_cast<uint4*>(VH + row * FST_ + lc) = h4;
        *reinterpret_cast<uint4*>(VL + row * FST_ + lc) = l4;
    }
    __syncthreads();

    // ---- lift Q fragments to registers ----
    uint32_t qh[8][4], ql[8][4];
    #pragma unroll
    for (int kk = 0; kk < 8; kk++) {
        int base0 = (wrow + g) * FST_ + kk * 8;
        int base1 = (wrow + 8 + g) * FST_ + kk * 8;
        qh[kk][0] = VH[base0 + tig];
        qh[kk][1] = VH[base1 + tig];
        qh[kk][2] = VH[base0 + tig + 4];
        qh[kk][3] = VH[base1 + tig + 4];
        ql[kk][0] = VL[base0 + tig];
        ql[kk][1] = VL[base1 + tig];
        ql[kk][2] = VL[base0 + tig + 4];
        ql[kk][3] = VL[base1 + tig + 4];
    }

    // ---- per-row mask params (rows r0 via c0/c1, r1 via c2/c3) ----
    const int r0 = i0 + wrow + g;
    const int r1 = r0 + 8;
    int qlo0 = 0, qhi0 = 0, qloL0 = 0, qlo1 = 0, qhi1 = 0, qloL1 = 0;
    if (!qleaf) {
        int nq0 = min(r0 - TK_, NK_ - 1);
        qlo0 = node_indices[((size_t)bh * NK_ + nq0) * 2 + 0];
        qhi0 = node_indices[((size_t)bh * NK_ + nq0) * 2 + 1];
        qloL0 = (node_pad[b * NK_ + nq0] != 0) ? (1 << 28) : qlo0;
        int nq1 = min(r1 - TK_, NK_ - 1);
        qlo1 = node_indices[((size_t)bh * NK_ + nq1) * 2 + 0];
        qhi1 = node_indices[((size_t)bh * NK_ + nq1) * 2 + 1];
        qloL1 = (node_pad[b * NK_ + nq1] != 0) ? (1 << 28) : qlo1;
    }

    float m0 = -1e30f, m1 = -1e30f, lsum0 = 0.f, lsum1 = 0.f;
    float acc[8][4] = {};

    const int ntiles = qleaf ? 8 : (9 + (i0 - TK_) / 64);
    for (int jt = 0; jt < ntiles; jt++) {
        const bool nodetile = (jt >= 8);
        const int j0 = nodetile ? TK_ + (jt - 8) * 64 : jt * 64;

        __syncthreads();   // previous tile's PV reads (K-as-P, V) complete
        // ---- K tile: plain [j][k] ----
        #pragma unroll
        for (int p = 0; p < 8; p++) {
            int row = p * 8 + lj;
            int gj = j0 + row;
            float4 kv = make_float4(0.f, 0.f, 0.f, 0.f);
            if (gj < L_)
                kv = *reinterpret_cast<const float4*>(g_k + ((size_t)bh * L_ + gj) * HD_ + lc);
            uint4 h4, l4;
            split_tf32(kv.x, h4.x, l4.x);
            split_tf32(kv.y, h4.y, l4.y);
            split_tf32(kv.z, h4.z, l4.z);
            split_tf32(kv.w, h4.w, l4.w);
            *reinterpret_cast<uint4*>(KH + row * FST_ + lc) = h4;
            *reinterpret_cast<uint4*>(KL + row * FST_ + lc) = l4;
        }
        // ---- V tile (row-major [j][d]) ----
        #pragma unroll
        for (int p = 0; p < 8; p++) {
            int row = p * 8 + lj;
            int gj = j0 + row;
            float4 vv = make_float4(0.f, 0.f, 0.f, 0.f);
            if (gj < L_)
                vv = *reinterpret_cast<const float4*>(g_v + ((size_t)bh * L_ + gj) * HD_ + lc);
            uint4 h4, l4;
            split_tf32(vv.x, h4.x, l4.x);
            split_tf32(vv.y, h4.y, l4.y);
            split_tf32(vv.z, h4.z, l4.z);
            split_tf32(vv.w, h4.w, l4.w);
            *reinterpret_cast<uint4*>(VH + row * FST_ + lc) = h4;
            *reinterpret_cast<uint4*>(VL + row * FST_ + lc) = l4;
        }
        if (nodetile && tid < 64) {
            int gj = j0 + tid;
            int nj = gj - TK_;
            int lo = (1 << 28), hi = -(1 << 28);
            if (nj < NK_ && gj < L_ && node_pad[b * NK_ + nj] == 0) {
                lo = node_indices[((size_t)bh * NK_ + nj) * 2 + 0];
                hi = node_indices[((size_t)bh * NK_ + nj) * 2 + 1];
            }
            clo[tid] = lo;
            chi[tid] = hi;
        }
        __syncthreads();

        // ---- S = Q K^T ----
        float s[8][4];
        #pragma unroll
        for (int nf = 0; nf < 8; nf++) {
            s[nf][0] = 0.f; s[nf][1] = 0.f; s[nf][2] = 0.f; s[nf][3] = 0.f;
        }
        for (int kk = 0; kk < 8; kk++) {
            #pragma unroll
            for (int nf = 0; nf < 8; nf++) {
                int nb = (nf * 8 + g) * FST_ + kk * 8;
                uint32_t bhv[2] = {KH[nb + tig], KH[nb + tig + 4]};
                uint32_t blv[2] = {KL[nb + tig], KL[nb + tig + 4]};
                MMA_TF32(s[nf], qh[kk], bhv);
                MMA_TF32(s[nf], qh[kk], blv);
                MMA_TF32(s[nf], ql[kk], bhv);
            }
        }

        // ---- mask ----
        if (qleaf) {
            #pragma unroll
            for (int nf = 0; nf < 8; nf++) {
                int gj = j0 + nf * 8 + 2 * tig;
                if (key_pad[b * TK_ + gj])     { s[nf][0] = -1e30f; s[nf][2] = -1e30f; }
                if (key_pad[b * TK_ + gj + 1]) { s[nf][1] = -1e30f; s[nf][3] = -1e30f; }
            }
        } else if (!nodetile) {
            #pragma unroll
            for (int nf = 0; nf < 8; nf++) {
                int gj = j0 + nf * 8 + 2 * tig;
                bool kp0 = (key_pad[b * TK_ + gj] != 0);
                bool kp1 = (key_pad[b * TK_ + gj + 1] != 0);
                if (!(gj >= qloL0 && gj <= qhi0 && !kp0))             s[nf][0] = -1e30f;
                if (!((gj + 1) >= qloL0 && (gj + 1) <= qhi0 && !kp1)) s[nf][1] = -1e30f;
                if (!(gj >= qloL1 && gj <= qhi1 && !kp0))             s[nf][2] = -1e30f;
                if (!((gj + 1) >= qloL1 && (gj + 1) <= qhi1 && !kp1)) s[nf][3] = -1e30f;
            }
        } else {
            int nq0 = r0 - TK_, nq1 = r1 - TK_;
            #pragma unroll
            for (int nf = 0; nf < 8; nf++) {
                int cj = nf * 8 + 2 * tig;
                int nj0 = j0 + cj - TK_;
                int lo20 = clo[cj],     hi20 = chi[cj];
                int lo21 = clo[cj + 1], hi21 = chi[cj + 1];
                if (!(nj0 <= nq0 && max(qlo0, lo20) <= min(qhi0, hi20)))     s[nf][0] = -1e30f;
                if (!(nj0 + 1 <= nq0 && max(qlo0, lo21) <= min(qhi0, hi21))) s[nf][1] = -1e30f;
                if (!(nj0 <= nq1 && max(qlo1, lo20) <= min(qhi1, hi20)))     s[nf][2] = -1e30f;
                if (!(nj0 + 1 <= nq1 && max(qlo1, lo21) <= min(qhi1, hi21))) s[nf][3] = -1e30f;
            }
        }

        // ---- online softmax ----
        float tm0 = -1e30f, tm1 = -1e30f;
        #pragma unroll
        for (int nf = 0; nf < 8; nf++) {
            tm0 = fmaxf(tm0, fmaxf(s[nf][0], s[nf][1]));
            tm1 = fmaxf(tm1, fmaxf(s[nf][2], s[nf][3]));
        }
        tm0 = fmaxf(tm0, __shfl_xor_sync(0xffffffffu, tm0, 1));
        tm0 = fmaxf(tm0, __shfl_xor_sync(0xffffffffu, tm0, 2));
        tm1 = fmaxf(tm1, __shfl_xor_sync(0xffffffffu, tm1, 1));
        tm1 = fmaxf(tm1, __shfl_xor_sync(0xffffffffu, tm1, 2));

        float mn0 = fmaxf(m0, tm0);
        float mn1 = fmaxf(m1, tm1);
        float a0 = __expf(m0 - mn0);
        float a1 = __expf(m1 - mn1);
        m0 = mn0; m1 = mn1;
        float sb0 = fmaxf(mn0, -1e20f);
        float sb1 = fmaxf(mn1, -1e20f);

        float rs0 = 0.f, rs1 = 0.f;
        #pragma unroll
        for (int nf = 0; nf < 8; nf++) {
            s[nf][0] = __expf(s[nf][0] - sb0);
            s[nf][1] = __expf(s[nf][1] - sb0);
            s[nf][2] = __expf(s[nf][2] - sb1);
            s[nf][3] = __expf(s[nf][3] - sb1);
            rs0 += s[nf][0] + s[nf][1];
            rs1 += s[nf][2] + s[nf][3];
        }
        rs0 += __shfl_xor_sync(0xffffffffu, rs0, 1);
        rs0 += __shfl_xor_sync(0xffffffffu, rs0, 2);
        rs1 += __shfl_xor_sync(0xffffffffu, rs1, 1);
        rs1 += __shfl_xor_sync(0xffffffffu, rs1, 2);
        lsum0 = lsum0 * a0 + rs0;
        lsum1 = lsum1 * a1 + rs1;
        #pragma unroll
        for (int nf = 0; nf < 8; nf++) {
            acc[nf][0] *= a0; acc[nf][1] *= a0;
            acc[nf][2] *= a1; acc[nf][3] *= a1;
        }

        // ---- ALL warps done reading K; write P into the K buffer ----
        __syncthreads();
        #pragma unroll
        for (int nf = 0; nf < 8; nf++) {
            int bg  = (wrow + g) * FST_ + nf * 8 + 2 * tig;
            int bg8 = (wrow + 8 + g) * FST_ + nf * 8 + 2 * tig;
            uint32_t h0, l0, h1, l1;
            split_tf32(s[nf][0], h0, l0);
            split_tf32(s[nf][1], h1, l1);
            *reinterpret_cast<uint2*>(KH + bg) = make_uint2(h0, h1);
            *reinterpret_cast<uint2*>(KL + bg) = make_uint2(l0, l1);
            split_tf32(s[nf][2], h0, l0);
            split_tf32(s[nf][3], h1, l1);
            *reinterpret_cast<uint2*>(KH + bg8) = make_uint2(h0, h1);
            *reinterpret_cast<uint2*>(KL + bg8) = make_uint2(l0, l1);
        }
        __syncwarp();      // each warp reads back only its own 16 rows

        // ---- acc += P V   (P in K buffer; B[k=j][n=d] = row-major V[j][d]) ----
        for (int kk = 0; kk < 8; kk++) {
            int base0 = (wrow + g) * FST_ + kk * 8;
            int base1 = (wrow + 8 + g) * FST_ + kk * 8;
            uint32_t ah[4] = {KH[base0 + tig], KH[base1 + tig],
                              KH[base0 + tig + 4], KH[base1 + tig + 4]};
            uint32_t al[4] = {KL[base0 + tig], KL[base1 + tig],
                              KL[base0 + tig + 4], KL[base1 + tig + 4]};
            #pragma unroll
            for (int nf = 0; nf < 8; nf++) {
                int vb0 = (kk * 8 + tig) * FST_ + nf * 8 + g;
                int vb1 = (kk * 8 + tig + 4) * FST_ + nf * 8 + g;
                uint32_t bhv[2] = {VH[vb0], VH[vb1]};
                uint32_t blv[2] = {VL[vb0], VL[vb1]};
                MMA_TF32(acc[nf], ah, bhv);
                MMA_TF32(acc[nf], ah, blv);
                MMA_TF32(acc[nf], al, bhv);
            }
        }
    }

    // ---- epilogue ----
    float inv0 = 1.0f / lsum0;
    float inv1 = 1.0f / lsum1;
    #pragma unroll
    for (int nf = 0; nf < 8; nf++) {
        int d0 = nf * 8 + 2 * tig;
        if (r0 < L_) {
            float2 v = make_float2(acc[nf][0] * inv0, acc[nf][1] * inv0);
            *reinterpret_cast<float2*>(g_ao + ((size_t)(b * L_ + r0)) * D_ + h * HD_ + d0) = v;
        }
        if (r1 < L_) {
            float2 v = make_float2(acc[nf][2] * inv1, acc[nf][3] * inv1);
            *reinterpret_cast<float2*>(g_ao + ((size_t)(b * L_ + r1)) * D_ + h * HD_ + d0) = v;
        }
    }
}

// ---------------------------------------------------------------------------
extern "C" void kernel_launch(void* const* d_in, const int* in_sizes, int n_in,
                              void* d_out, int out_size)
{
    const float* leaves = (const float*)d_in[0];
    const float* nodes  = (const float*)d_in[1];
    const float* Wq     = (const float*)d_in[2];
    const float* Wk     = (const float*)d_in[3];
    const float* Wv     = (const float*)d_in[4];
    const float* Wo     = (const float*)d_in[5];
    const float* bq     = (const float*)d_in[6];
    const float* bk     = (const float*)d_in[7];
    const float* bv     = (const float*)d_in[8];
    const float* bo     = (const float*)d_in[9];
    const int*   node_indices = (const int*)d_in[10];
    const unsigned char* key_pad  = (const unsigned char*)d_in[11];
    const unsigned char* node_pad = (const unsigned char*)d_in[12];
    float* out = (float*)d_out;

    static int smem_set = 0;
    if (!smem_set) {
        cudaFuncSetAttribute(flash_mma_kernel,
                             cudaFuncAttributeMaxDynamicSharedMemorySize,
                             FLASH_SMEM);
        cudaFuncSetAttribute(qkv_mma_kernel,
                             cudaFuncAttributeMaxDynamicSharedMemorySize,
                             GEMM_SMEM_BYTES);
        cudaFuncSetAttribute(oproj_mma_kernel,
                             cudaFuncAttributeMaxDynamicSharedMemorySize,
                             GEMM_SMEM_BYTES);
        smem_set = 1;
    }

    qkv_mma_kernel<<<dim3(8, 32, 3), 256, GEMM_SMEM_BYTES>>>(
        leaves, nodes, Wq, Wk, Wv, bq, bk, bv);
    flash_mma_kernel<<<dim3(16, 32), 128, FLASH_SMEM>>>(node_indices, key_pad, node_pad);
    oproj_mma_kernel<<<dim3(8, 32), 256, GEMM_SMEM_BYTES>>>(Wo, bo, out);
}

// round 11
// speedup vs baseline: 1.2100x; 1.0639x over previous
#include <cuda_runtime.h>
#include <cstdint>

#define B_    4
#define H_    8
#define TK_   512
#define NK_   511
#define L_    1023
#define D_    512
#define HD_   64
#define BH_   32
#define ROWS_ 4092          // B_*L_

// Scratch (static __device__ — no allocations allowed)
__device__ float g_q[B_*H_*L_*HD_];
__device__ float g_k[B_*H_*L_*HD_];
__device__ float g_v[B_*H_*L_*HD_];
__device__ float g_ao[B_*L_*D_];            // attention output, (B,L, H*HD)

// ---------------------------------------------------------------------------
// tf32 helpers
// ---------------------------------------------------------------------------
__device__ __forceinline__ void split_tf32(float x, uint32_t& hi, uint32_t& lo)
{
    float h, l2;
    asm("cvt.rna.tf32.f32 %0, %1;" : "=f"(h) : "f"(x));
    float l = x - h;
    asm("cvt.rna.tf32.f32 %0, %1;" : "=f"(l2) : "f"(l));
    hi = __float_as_uint(h);
    lo = __float_as_uint(l2);
}

#define MMA_TF32(d, a, b)                                                     \
    asm volatile(                                                             \
        "mma.sync.aligned.m16n8k8.row.col.f32.tf32.tf32.f32 "                 \
        "{%0,%1,%2,%3}, {%4,%5,%6,%7}, {%8,%9}, {%0,%1,%2,%3};"               \
        : "+f"((d)[0]), "+f"((d)[1]), "+f"((d)[2]), "+f"((d)[3])              \
        : "r"((a)[0]), "r"((a)[1]), "r"((a)[2]), "r"((a)[3]),                 \
          "r"((b)[0]), "r"((b)[1]))

// ldmatrix x4: 4 8x8 b16 matrices; lane j of each matrix gets row j/4, tf32
// column j%4 — exactly the tf32 mma fragment layout.
#define LDSM_X4(R0, R1, R2, R3, ADDR)                                         \
    asm volatile("ldmatrix.sync.aligned.m8n8.x4.shared.b16 {%0,%1,%2,%3}, [%4];" \
        : "=r"(R0), "=r"(R1), "=r"(R2), "=r"(R3) : "r"(ADDR))

__device__ __forceinline__ uint32_t smem_u32(const void* p)
{
    return (uint32_t)__cvta_generic_to_shared(p);
}

// GEMM kernels: k-chunk = 32 -> stride 36
#define AST_ 36
#define GEMM_SMEM_BYTES ((2*128*AST_ + 2*64*AST_) * 4)   // 55296
// Flash tiles hold full k=64 -> stride 68 (proven in round 7)
#define FST_ 68
#define FLASH_SMEM (6*64*FST_*4 + 2*64*4)                // 104960

// ---------------------------------------------------------------------------
// Kernel 1: fused QKV projection via tf32x3 tensor-core GEMM.
// Fragment loads via ldmatrix (one LDSM.x4 replaces 16 scalar LDS).
// ---------------------------------------------------------------------------
__global__ void __launch_bounds__(256, 2)
qkv_mma_kernel(const float* __restrict__ leaves,
               const float* __restrict__ nodes,
               const float* __restrict__ Wq,
               const float* __restrict__ Wk,
               const float* __restrict__ Wv,
               const float* __restrict__ bq,
               const float* __restrict__ bk,
               const float* __restrict__ bv)
{
    const int z = blockIdx.z;
    const float* W    = (z == 0) ? Wq : (z == 1) ? Wk : Wv;
    const float* bias = (z == 0) ? bq : (z == 1) ? bk : bv;
    float* out        = (z == 0) ? g_q : (z == 1) ? g_k : g_v;
    const float scale = (z == 0) ? 0.125f : 1.0f;

    extern __shared__ uint32_t smem_u[];
    uint32_t* AH = smem_u;
    uint32_t* AL = AH + 128 * AST_;
    uint32_t* BH = AL + 128 * AST_;
    uint32_t* BL = BH + 64 * AST_;

    const int tid  = threadIdx.x;
    const int warp = tid >> 5;
    const int lane = tid & 31;
    const int g    = lane >> 2;
    const int tig  = lane & 3;
    const int warpM = warp & 3;
    const int warpN = warp >> 2;
    const int M0 = warpM * 32;
    const int N0 = warpN * 32;

    const int r0 = blockIdx.y * 128;
    const int c0 = blockIdx.x * 64;

    const int lm = tid >> 3;
    const int lk = (tid & 7) * 4;

    // ldmatrix per-lane source rows:
    //   A x4: m0 rows+0 k+0 | m1 rows+8 k+0 | m2 rows+0 k+4 | m3 rows+8 k+4
    //   B x4: m0 nt rows k+0 | m1 nt rows k+4 | m2 nt+1 rows k+0 | m3 nt+1 k+4
    const int r8 = lane & 7;
    const int mi = lane >> 3;
    const int rowA = (mi & 1) * 8 + r8, kA = (mi >> 1) * 4;
    const int rowB = (mi >> 1) * 8 + r8, kB = (mi & 1) * 4;
    const uint32_t ah_addr = smem_u32(AH) + (((M0 + rowA) * AST_ + kA) << 2);
    const uint32_t al_addr = smem_u32(AL) + (((M0 + rowA) * AST_ + kA) << 2);
    const uint32_t bh_addr = smem_u32(BH) + (((N0 + rowB) * AST_ + kB) << 2);
    const uint32_t bl_addr = smem_u32(BL) + (((N0 + rowB) * AST_ + kB) << 2);
    const uint32_t MT_STEP = (16 * AST_) << 2;

    const float* xsrc[4];
    #pragma unroll
    for (int p = 0; p < 4; p++) {
        int gr = r0 + lm + p * 32;
        if (gr < ROWS_) {
            int b = gr / L_, t = gr % L_;
            xsrc[p] = (t < TK_) ? (leaves + ((size_t)(b * TK_ + t)) * D_)
                                : (nodes  + ((size_t)(b * NK_ + (t - TK_))) * D_);
        } else xsrc[p] = nullptr;
    }
    const float* wsrc0 = W + (size_t)(c0 + lm) * D_;
    const float* wsrc1 = W + (size_t)(c0 + lm + 32) * D_;

    float acc[2][4][4] = {};

    float4 xa[4], wb[2];
    #pragma unroll
    for (int p = 0; p < 4; p++) {
        xa[p] = make_float4(0.f, 0.f, 0.f, 0.f);
        if (xsrc[p]) xa[p] = *reinterpret_cast<const float4*>(xsrc[p] + lk);
    }
    wb[0] = *reinterpret_cast<const float4*>(wsrc0 + lk);
    wb[1] = *reinterpret_cast<const float4*>(wsrc1 + lk);

    for (int k0 = 0; k0 < D_; k0 += 32) {
        __syncthreads();
        #pragma unroll
        for (int p = 0; p < 4; p++) {
            uint4 h4, l4;
            split_tf32(xa[p].x, h4.x, l4.x);
            split_tf32(xa[p].y, h4.y, l4.y);
            split_tf32(xa[p].z, h4.z, l4.z);
            split_tf32(xa[p].w, h4.w, l4.w);
            int m = lm + p * 32;
            *reinterpret_cast<uint4*>(AH + m * AST_ + lk) = h4;
            *reinterpret_cast<uint4*>(AL + m * AST_ + lk) = l4;
        }
        #pragma unroll
        for (int p = 0; p < 2; p++) {
            uint4 h4, l4;
            split_tf32(wb[p].x, h4.x, l4.x);
            split_tf32(wb[p].y, h4.y, l4.y);
            split_tf32(wb[p].z, h4.z, l4.z);
            split_tf32(wb[p].w, h4.w, l4.w);
            int n = lm + p * 32;
            *reinterpret_cast<uint4*>(BH + n * AST_ + lk) = h4;
            *reinterpret_cast<uint4*>(BL + n * AST_ + lk) = l4;
        }
        __syncthreads();

        if (k0 + 32 < D_) {
            #pragma unroll
            for (int p = 0; p < 4; p++) {
                if (xsrc[p]) xa[p] = *reinterpret_cast<const float4*>(xsrc[p] + k0 + 32 + lk);
            }
            wb[0] = *reinterpret_cast<const float4*>(wsrc0 + k0 + 32 + lk);
            wb[1] = *reinterpret_cast<const float4*>(wsrc1 + k0 + 32 + lk);
        }

        #pragma unroll
        for (int ks = 0; ks < 4; ks++) {
            const uint32_t koff = (ks * 8) << 2;
            uint32_t ah[2][4], al[2][4], bh[4][2], bl[4][2];
            LDSM_X4(ah[0][0], ah[0][1], ah[0][2], ah[0][3], ah_addr + koff);
            LDSM_X4(ah[1][0], ah[1][1], ah[1][2], ah[1][3], ah_addr + MT_STEP + koff);
            LDSM_X4(al[0][0], al[0][1], al[0][2], al[0][3], al_addr + koff);
            LDSM_X4(al[1][0], al[1][1], al[1][2], al[1][3], al_addr + MT_STEP + koff);
            uint32_t t0, t1, t2, t3;
            LDSM_X4(t0, t1, t2, t3, bh_addr + koff);
            bh[0][0] = t0; bh[0][1] = t1; bh[1][0] = t2; bh[1][1] = t3;
            LDSM_X4(t0, t1, t2, t3, bh_addr + MT_STEP + koff);
            bh[2][0] = t0; bh[2][1] = t1; bh[3][0] = t2; bh[3][1] = t3;
            LDSM_X4(t0, t1, t2, t3, bl_addr + koff);
            bl[0][0] = t0; bl[0][1] = t1; bl[1][0] = t2; bl[1][1] = t3;
            LDSM_X4(t0, t1, t2, t3, bl_addr + MT_STEP + koff);
            bl[2][0] = t0; bl[2][1] = t1; bl[3][0] = t2; bl[3][1] = t3;

            #pragma unroll
            for (int mt = 0; mt < 2; mt++)
                #pragma unroll
                for (int nt = 0; nt < 4; nt++) {
                    MMA_TF32(acc[mt][nt], ah[mt], bh[nt]);
                    MMA_TF32(acc[mt][nt], ah[mt], bl[nt]);
                    MMA_TF32(acc[mt][nt], al[mt], bh[nt]);
                }
        }
    }

    #pragma unroll
    for (int mt = 0; mt < 2; mt++)
        #pragma unroll
        for (int nt = 0; nt < 4; nt++) {
            int col = N0 + nt * 8 + tig * 2;
            int gc = c0 + col;
            int h = gc >> 6, d = gc & 63;
            float b0v = bias[gc], b1v = bias[gc + 1];
            #pragma unroll
            for (int hh = 0; hh < 2; hh++) {
                int gr = r0 + M0 + mt * 16 + g + hh * 8;
                if (gr >= ROWS_) continue;
                int b = gr / L_, l = gr % L_;
                float v0 = (acc[mt][nt][hh * 2 + 0] + b0v) * scale;
                float v1 = (acc[mt][nt][hh * 2 + 1] + b1v) * scale;
                float* dst = out + (((size_t)(b * H_ + h)) * L_ + l) * HD_ + d;
                dst[0] = v0;
                dst[1] = v1;
            }
        }
}

// ---------------------------------------------------------------------------
// Kernel 3: out = g_ao @ Wo^T + bo  (ldmatrix fragment loads)
// ---------------------------------------------------------------------------
__global__ void __launch_bounds__(256, 2)
oproj_mma_kernel(const float* __restrict__ Wo,
                 const float* __restrict__ bo,
                 float* __restrict__ out)
{
    extern __shared__ uint32_t smem_u[];
    uint32_t* AH = smem_u;
    uint32_t* AL = AH + 128 * AST_;
    uint32_t* BH = AL + 128 * AST_;
    uint32_t* BL = BH + 64 * AST_;

    const int tid  = threadIdx.x;
    const int warp = tid >> 5;
    const int lane = tid & 31;
    const int g    = lane >> 2;
    const int tig  = lane & 3;
    const int warpM = warp & 3;
    const int warpN = warp >> 2;
    const int M0 = warpM * 32;
    const int N0 = warpN * 32;

    const int r0 = blockIdx.y * 128;
    const int c0 = blockIdx.x * 64;

    const int lm = tid >> 3;
    const int lk = (tid & 7) * 4;

    const int r8 = lane & 7;
    const int mi = lane >> 3;
    const int rowA = (mi & 1) * 8 + r8, kA = (mi >> 1) * 4;
    const int rowB = (mi >> 1) * 8 + r8, kB = (mi & 1) * 4;
    const uint32_t ah_addr = smem_u32(AH) + (((M0 + rowA) * AST_ + kA) << 2);
    const uint32_t al_addr = smem_u32(AL) + (((M0 + rowA) * AST_ + kA) << 2);
    const uint32_t bh_addr = smem_u32(BH) + (((N0 + rowB) * AST_ + kB) << 2);
    const uint32_t bl_addr = smem_u32(BL) + (((N0 + rowB) * AST_ + kB) << 2);
    const uint32_t MT_STEP = (16 * AST_) << 2;

    const float* xsrc[4];
    #pragma unroll
    for (int p = 0; p < 4; p++) {
        int gr = r0 + lm + p * 32;
        xsrc[p] = (gr < ROWS_) ? (g_ao + (size_t)gr * D_) : nullptr;
    }
    const float* wsrc0 = Wo + (size_t)(c0 + lm) * D_;
    const float* wsrc1 = Wo + (size_t)(c0 + lm + 32) * D_;

    float acc[2][4][4] = {};

    float4 xa[4], wb[2];
    #pragma unroll
    for (int p = 0; p < 4; p++) {
        xa[p] = make_float4(0.f, 0.f, 0.f, 0.f);
        if (xsrc[p]) xa[p] = *reinterpret_cast<const float4*>(xsrc[p] + lk);
    }
    wb[0] = *reinterpret_cast<const float4*>(wsrc0 + lk);
    wb[1] = *reinterpret_cast<const float4*>(wsrc1 + lk);

    for (int k0 = 0; k0 < D_; k0 += 32) {
        __syncthreads();
        #pragma unroll
        for (int p = 0; p < 4; p++) {
            uint4 h4, l4;
            split_tf32(xa[p].x, h4.x, l4.x);
            split_tf32(xa[p].y, h4.y, l4.y);
            split_tf32(xa[p].z, h4.z, l4.z);
            split_tf32(xa[p].w, h4.w, l4.w);
            int m = lm + p * 32;
            *reinterpret_cast<uint4*>(AH + m * AST_ + lk) = h4;
            *reinterpret_cast<uint4*>(AL + m * AST_ + lk) = l4;
        }
        #pragma unroll
        for (int p = 0; p < 2; p++) {
            uint4 h4, l4;
            split_tf32(wb[p].x, h4.x, l4.x);
            split_tf32(wb[p].y, h4.y, l4.y);
            split_tf32(wb[p].z, h4.z, l4.z);
            split_tf32(wb[p].w, h4.w, l4.w);
            int n = lm + p * 32;
            *reinterpret_cast<uint4*>(BH + n * AST_ + lk) = h4;
            *reinterpret_cast<uint4*>(BL + n * AST_ + lk) = l4;
        }
        __syncthreads();

        if (k0 + 32 < D_) {
            #pragma unroll
            for (int p = 0; p < 4; p++) {
                if (xsrc[p]) xa[p] = *reinterpret_cast<const float4*>(xsrc[p] + k0 + 32 + lk);
            }
            wb[0] = *reinterpret_cast<const float4*>(wsrc0 + k0 + 32 + lk);
            wb[1] = *reinterpret_cast<const float4*>(wsrc1 + k0 + 32 + lk);
        }

        #pragma unroll
        for (int ks = 0; ks < 4; ks++) {
            const uint32_t koff = (ks * 8) << 2;
            uint32_t ah[2][4], al[2][4], bh[4][2], bl[4][2];
            LDSM_X4(ah[0][0], ah[0][1], ah[0][2], ah[0][3], ah_addr + koff);
            LDSM_X4(ah[1][0], ah[1][1], ah[1][2], ah[1][3], ah_addr + MT_STEP + koff);
            LDSM_X4(al[0][0], al[0][1], al[0][2], al[0][3], al_addr + koff);
            LDSM_X4(al[1][0], al[1][1], al[1][2], al[1][3], al_addr + MT_STEP + koff);
            uint32_t t0, t1, t2, t3;
            LDSM_X4(t0, t1, t2, t3, bh_addr + koff);
            bh[0][0] = t0; bh[0][1] = t1; bh[1][0] = t2; bh[1][1] = t3;
            LDSM_X4(t0, t1, t2, t3, bh_addr + MT_STEP + koff);
            bh[2][0] = t0; bh[2][1] = t1; bh[3][0] = t2; bh[3][1] = t3;
            LDSM_X4(t0, t1, t2, t3, bl_addr + koff);
            bl[0][0] = t0; bl[0][1] = t1; bl[1][0] = t2; bl[1][1] = t3;
            LDSM_X4(t0, t1, t2, t3, bl_addr + MT_STEP + koff);
            bl[2][0] = t0; bl[2][1] = t1; bl[3][0] = t2; bl[3][1] = t3;

            #pragma unroll
            for (int mt = 0; mt < 2; mt++)
                #pragma unroll
                for (int nt = 0; nt < 4; nt++) {
                    MMA_TF32(acc[mt][nt], ah[mt], bh[nt]);
                    MMA_TF32(acc[mt][nt], ah[mt], bl[nt]);
                    MMA_TF32(acc[mt][nt], al[mt], bh[nt]);
                }
        }
    }

    #pragma unroll
    for (int mt = 0; mt < 2; mt++)
        #pragma unroll
        for (int nt = 0; nt < 4; nt++) {
            int gc = c0 + N0 + nt * 8 + tig * 2;
            float b0v = bo[gc], b1v = bo[gc + 1];
            #pragma unroll
            for (int hh = 0; hh < 2; hh++) {
                int gr = r0 + M0 + mt * 16 + g + hh * 8;
                if (gr >= ROWS_) continue;
                float* dst = out + (size_t)gr * D_ + gc;
                dst[0] = acc[mt][nt][hh * 2 + 0] + b0v;
                dst[1] = acc[mt][nt][hh * 2 + 1] + b1v;
            }
        }
}

// ---------------------------------------------------------------------------
// Kernel 2: flash attention — ROUND-7 VERBATIM (proven 342.5 configuration).
// ---------------------------------------------------------------------------
__global__ void flash_mma_kernel(const int* __restrict__ node_indices,
                                 const unsigned char* __restrict__ key_pad,
                                 const unsigned char* __restrict__ node_pad)
{
    extern __shared__ uint32_t sm[];
    uint32_t* KH = sm;
    uint32_t* KL = KH + 64 * FST_;
    uint32_t* VH = KL + 64 * FST_;
    uint32_t* VL = VH + 64 * FST_;
    uint32_t* PH = VL + 64 * FST_;
    uint32_t* PL = PH + 64 * FST_;
    int* clo = (int*)(PL + 64 * FST_);
    int* chi = clo + 64;

    const int bh = blockIdx.y;
    const int b  = bh >> 3;
    const int h  = bh & 7;
    const int i0 = blockIdx.x * 64;
    const bool qleaf = (i0 < TK_);

    const int tid  = threadIdx.x;       // 128
    const int warp = tid >> 5;
    const int lane = tid & 31;
    const int g    = lane >> 2;
    const int tig  = lane & 3;
    const int wrow = warp * 16;

    const int lj = tid >> 4;            // 0..7
    const int lc = (tid & 15) * 4;      // 0,4,...,60

    #pragma unroll
    for (int p = 0; p < 8; p++) {
        int row = p * 8 + lj;
        int gi = i0 + row;
        float4 qv = make_float4(0.f, 0.f, 0.f, 0.f);
        if (gi < L_)
            qv = *reinterpret_cast<const float4*>(g_q + ((size_t)bh * L_ + gi) * HD_ + lc);
        uint4 h4, l4;
        split_tf32(qv.x, h4.x, l4.x);
        split_tf32(qv.y, h4.y, l4.y);
        split_tf32(qv.z, h4.z, l4.z);
        split_tf32(qv.w, h4.w, l4.w);
        *reinterpret_cast<uint4*>(PH + row * FST_ + lc) = h4;
        *reinterpret_cast<uint4*>(PL + row * FST_ + lc) = l4;
    }
    __syncthreads();

    uint32_t qh[8][4], ql[8][4];
    #pragma unroll
    for (int kk = 0; kk < 8; kk++) {
        int base0 = (wrow + g) * FST_ + kk * 8;
        int base1 = (wrow + 8 + g) * FST_ + kk * 8;
        qh[kk][0] = PH[base0 + tig];
        qh[kk][1] = PH[base1 + tig];
        qh[kk][2] = PH[base0 + tig + 4];
        qh[kk][3] = PH[base1 + tig + 4];
        ql[kk][0] = PL[base0 + tig];
        ql[kk][1] = PL[base1 + tig];
        ql[kk][2] = PL[base0 + tig + 4];
        ql[kk][3] = PL[base1 + tig + 4];
    }

    const int r0 = i0 + wrow + g;
    const int r1 = r0 + 8;
    int qlo0 = 0, qhi0 = 0, qloL0 = 0, qlo1 = 0, qhi1 = 0, qloL1 = 0;
    if (!qleaf) {
        int nq0 = min(r0 - TK_, NK_ - 1);
        qlo0 = node_indices[((size_t)bh * NK_ + nq0) * 2 + 0];
        qhi0 = node_indices[((size_t)bh * NK_ + nq0) * 2 + 1];
        qloL0 = (node_pad[b * NK_ + nq0] != 0) ? (1 << 28) : qlo0;
        int nq1 = min(r1 - TK_, NK_ - 1);
        qlo1 = node_indices[((size_t)bh * NK_ + nq1) * 2 + 0];
        qhi1 = node_indices[((size_t)bh * NK_ + nq1) * 2 + 1];
        qloL1 = (node_pad[b * NK_ + nq1] != 0) ? (1 << 28) : qlo1;
    }

    float m0 = -1e30f, m1 = -1e30f, lsum0 = 0.f, lsum1 = 0.f;
    float acc[8][4] = {};

    const int ntiles = qleaf ? 8 : (9 + (i0 - TK_) / 64);
    for (int jt = 0; jt < ntiles; jt++) {
        const bool nodetile = (jt >= 8);
        const int j0 = nodetile ? TK_ + (jt - 8) * 64 : jt * 64;

        __syncthreads();
        #pragma unroll
        for (int p = 0; p < 8; p++) {
            int row = p * 8 + lj;
            int gj = j0 + row;
            float4 kv = make_float4(0.f, 0.f, 0.f, 0.f);
            if (gj < L_)
                kv = *reinterpret_cast<const float4*>(g_k + ((size_t)bh * L_ + gj) * HD_ + lc);
            uint4 h4, l4;
            split_tf32(kv.x, h4.x, l4.x);
            split_tf32(kv.y, h4.y, l4.y);
            split_tf32(kv.z, h4.z, l4.z);
            split_tf32(kv.w, h4.w, l4.w);
            *reinterpret_cast<uint4*>(KH + row * FST_ + lc) = h4;
            *reinterpret_cast<uint4*>(KL + row * FST_ + lc) = l4;
        }
        #pragma unroll
        for (int p = 0; p < 8; p++) {
            int row = p * 8 + lj;
            int gj = j0 + row;
            float4 vv = make_float4(0.f, 0.f, 0.f, 0.f);
            if (gj < L_)
                vv = *reinterpret_cast<const float4*>(g_v + ((size_t)bh * L_ + gj) * HD_ + lc);
            uint4 h4, l4;
            split_tf32(vv.x, h4.x, l4.x);
            split_tf32(vv.y, h4.y, l4.y);
            split_tf32(vv.z, h4.z, l4.z);
            split_tf32(vv.w, h4.w, l4.w);
            *reinterpret_cast<uint4*>(VH + row * FST_ + lc) = h4;
            *reinterpret_cast<uint4*>(VL + row * FST_ + lc) = l4;
        }
        if (nodetile && tid < 64) {
            int gj = j0 + tid;
            int nj = gj - TK_;
            int lo = (1 << 28), hi = -(1 << 28);
            if (nj < NK_ && gj < L_ && node_pad[b * NK_ + nj] == 0) {
                lo = node_indices[((size_t)bh * NK_ + nj) * 2 + 0];
                hi = node_indices[((size_t)bh * NK_ + nj) * 2 + 1];
            }
            clo[tid] = lo;
            chi[tid] = hi;
        }
        __syncthreads();

        float s[8][4];
        #pragma unroll
        for (int nf = 0; nf < 8; nf++) {
            s[nf][0] = 0.f; s[nf][1] = 0.f; s[nf][2] = 0.f; s[nf][3] = 0.f;
        }
        for (int kk = 0; kk < 8; kk++) {
            #pragma unroll
            for (int nf = 0; nf < 8; nf++) {
                int nb = (nf * 8 + g) * FST_ + kk * 8;
                uint32_t bhv[2] = {KH[nb + tig], KH[nb + tig + 4]};
                uint32_t blv[2] = {KL[nb + tig], KL[nb + tig + 4]};
                MMA_TF32(s[nf], qh[kk], bhv);
                MMA_TF32(s[nf], qh[kk], blv);
                MMA_TF32(s[nf], ql[kk], bhv);
            }
        }

        if (qleaf) {
            #pragma unroll
            for (int nf = 0; nf < 8; nf++) {
                int gj = j0 + nf * 8 + 2 * tig;
                if (key_pad[b * TK_ + gj])     { s[nf][0] = -1e30f; s[nf][2] = -1e30f; }
                if (key_pad[b * TK_ + gj + 1]) { s[nf][1] = -1e30f; s[nf][3] = -1e30f; }
            }
        } else if (!nodetile) {
            #pragma unroll
            for (int nf = 0; nf < 8; nf++) {
                int gj = j0 + nf * 8 + 2 * tig;
                bool kp0 = (key_pad[b * TK_ + gj] != 0);
                bool kp1 = (key_pad[b * TK_ + gj + 1] != 0);
                if (!(gj >= qloL0 && gj <= qhi0 && !kp0))             s[nf][0] = -1e30f;
                if (!((gj + 1) >= qloL0 && (gj + 1) <= qhi0 && !kp1)) s[nf][1] = -1e30f;
                if (!(gj >= qloL1 && gj <= qhi1 && !kp0))             s[nf][2] = -1e30f;
                if (!((gj + 1) >= qloL1 && (gj + 1) <= qhi1 && !kp1)) s[nf][3] = -1e30f;
            }
        } else {
            int nq0 = r0 - TK_, nq1 = r1 - TK_;
            #pragma unroll
            for (int nf = 0; nf < 8; nf++) {
                int cj = nf * 8 + 2 * tig;
                int nj0 = j0 + cj - TK_;
                int lo20 = clo[cj],     hi20 = chi[cj];
                int lo21 = clo[cj + 1], hi21 = chi[cj + 1];
                if (!(nj0 <= nq0 && max(qlo0, lo20) <= min(qhi0, hi20)))     s[nf][0] = -1e30f;
                if (!(nj0 + 1 <= nq0 && max(qlo0, lo21) <= min(qhi0, hi21))) s[nf][1] = -1e30f;
                if (!(nj0 <= nq1 && max(qlo1, lo20) <= min(qhi1, hi20)))     s[nf][2] = -1e30f;
                if (!(nj0 + 1 <= nq1 && max(qlo1, lo21) <= min(qhi1, hi21))) s[nf][3] = -1e30f;
            }
        }

        float tm0 = -1e30f, tm1 = -1e30f;
        #pragma unroll
        for (int nf = 0; nf < 8; nf++) {
            tm0 = fmaxf(tm0, fmaxf(s[nf][0], s[nf][1]));
            tm1 = fmaxf(tm1, fmaxf(s[nf][2], s[nf][3]));
        }
        tm0 = fmaxf(tm0, __shfl_xor_sync(0xffffffffu, tm0, 1));
        tm0 = fmaxf(tm0, __shfl_xor_sync(0xffffffffu, tm0, 2));
        tm1 = fmaxf(tm1, __shfl_xor_sync(0xffffffffu, tm1, 1));
        tm1 = fmaxf(tm1, __shfl_xor_sync(0xffffffffu, tm1, 2));

        float mn0 = fmaxf(m0, tm0);
        float mn1 = fmaxf(m1, tm1);
        float a0 = __expf(m0 - mn0);
        float a1 = __expf(m1 - mn1);
        m0 = mn0; m1 = mn1;
        float sb0 = fmaxf(mn0, -1e20f);
        float sb1 = fmaxf(mn1, -1e20f);

        float rs0 = 0.f, rs1 = 0.f;
        #pragma unroll
        for (int nf = 0; nf < 8; nf++) {
            s[nf][0] = __expf(s[nf][0] - sb0);
            s[nf][1] = __expf(s[nf][1] - sb0);
            s[nf][2] = __expf(s[nf][2] - sb1);
            s[nf][3] = __expf(s[nf][3] - sb1);
            rs0 += s[nf][0] + s[nf][1];
            rs1 += s[nf][2] + s[nf][3];
        }
        rs0 += __shfl_xor_sync(0xffffffffu, rs0, 1);
        rs0 += __shfl_xor_sync(0xffffffffu, rs0, 2);
        rs1 += __shfl_xor_sync(0xffffffffu, rs1, 1);
        rs1 += __shfl_xor_sync(0xffffffffu, rs1, 2);
        lsum0 = lsum0 * a0 + rs0;
        lsum1 = lsum1 * a1 + rs1;
        #pragma unroll
        for (int nf = 0; nf < 8; nf++) {
            acc[nf][0] *= a0; acc[nf][1] *= a0;
            acc[nf][2] *= a1; acc[nf][3] *= a1;
        }

        #pragma unroll
        for (int nf = 0; nf < 8; nf++) {
            int bg  = (wrow + g) * FST_ + nf * 8 + 2 * tig;
            int bg8 = (wrow + 8 + g) * FST_ + nf * 8 + 2 * tig;
            uint32_t h0, l0, h1, l1;
            split_tf32(s[nf][0], h0, l0);
            split_tf32(s[nf][1], h1, l1);
            *reinterpret_cast<uint2*>(PH + bg) = make_uint2(h0, h1);
            *reinterpret_cast<uint2*>(PL + bg) = make_uint2(l0, l1);
            split_tf32(s[nf][2], h0, l0);
            split_tf32(s[nf][3], h1, l1);
            *reinterpret_cast<uint2*>(PH + bg8) = make_uint2(h0, h1);
            *reinterpret_cast<uint2*>(PL + bg8) = make_uint2(l0, l1);
        }
        __syncwarp();

        for (int kk = 0; kk < 8; kk++) {
            int base0 = (wrow + g) * FST_ + kk * 8;
            int base1 = (wrow + 8 + g) * FST_ + kk * 8;
            uint32_t ah[4] = {PH[base0 + tig], PH[base1 + tig],
                              PH[base0 + tig + 4], PH[base1 + tig + 4]};
            uint32_t al[4] = {PL[base0 + tig], PL[base1 + tig],
                              PL[base0 + tig + 4], PL[base1 + tig + 4]};
            #pragma unroll
            for (int nf = 0; nf < 8; nf++) {
                int vb0 = (kk * 8 + tig) * FST_ + nf * 8 + g;
                int vb1 = (kk * 8 + tig + 4) * FST_ + nf * 8 + g;
                uint32_t bhv[2] = {VH[vb0], VH[vb1]};
                uint32_t blv[2] = {VL[vb0], VL[vb1]};
                MMA_TF32(acc[nf], ah, bhv);
                MMA_TF32(acc[nf], ah, blv);
                MMA_TF32(acc[nf], al, bhv);
            }
        }
    }

    float inv0 = 1.0f / lsum0;
    float inv1 = 1.0f / lsum1;
    #pragma unroll
    for (int nf = 0; nf < 8; nf++) {
        int d0 = nf * 8 + 2 * tig;
        if (r0 < L_) {
            float2 v = make_float2(acc[nf][0] * inv0, acc[nf][1] * inv0);
            *reinterpret_cast<float2*>(g_ao + ((size_t)(b * L_ + r0)) * D_ + h * HD_ + d0) = v;
        }
        if (r1 < L_) {
            float2 v = make_float2(acc[nf][2] * inv1, acc[nf][3] * inv1);
            *reinterpret_cast<float2*>(g_ao + ((size_t)(b * L_ + r1)) * D_ + h * HD_ + d0) = v;
        }
    }
}

// ---------------------------------------------------------------------------
extern "C" void kernel_launch(void* const* d_in, const int* in_sizes, int n_in,
                              void* d_out, int out_size)
{
    const float* leaves = (const float*)d_in[0];
    const float* nodes  = (const float*)d_in[1];
    const float* Wq     = (const float*)d_in[2];
    const float* Wk     = (const float*)d_in[3];
    const float* Wv     = (const float*)d_in[4];
    const float* Wo     = (const float*)d_in[5];
    const float* bq     = (const float*)d_in[6];
    const float* bk     = (const float*)d_in[7];
    const float* bv     = (const float*)d_in[8];
    const float* bo     = (const float*)d_in[9];
    const int*   node_indices = (const int*)d_in[10];
    const unsigned char* key_pad  = (const unsigned char*)d_in[11];
    const unsigned char* node_pad = (const unsigned char*)d_in[12];
    float* out = (float*)d_out;

    static int smem_set = 0;
    if (!smem_set) {
        cudaFuncSetAttribute(flash_mma_kernel,
                             cudaFuncAttributeMaxDynamicSharedMemorySize,
                             FLASH_SMEM);
        cudaFuncSetAttribute(qkv_mma_kernel,
                             cudaFuncAttributeMaxDynamicSharedMemorySize,
                             GEMM_SMEM_BYTES);
        cudaFuncSetAttribute(oproj_mma_kernel,
                             cudaFuncAttributeMaxDynamicSharedMemorySize,
                             GEMM_SMEM_BYTES);
        smem_set = 1;
    }

    qkv_mma_kernel<<<dim3(8, 32, 3), 256, GEMM_SMEM_BYTES>>>(
        leaves, nodes, Wq, Wk, Wv, bq, bk, bv);
    flash_mma_kernel<<<dim3(16, 32), 128, FLASH_SMEM>>>(node_indices, key_pad, node_pad);
    oproj_mma_kernel<<<dim3(8, 32), 256, GEMM_SMEM_BYTES>>>(Wo, bo, out);
}